// round 17
// baseline (speedup 1.0000x reference)
#include <cuda_runtime.h>
#include <cuda_fp16.h>
#include <cstdint>

#define Bn 32
#define Ln 512
#define Dn 512
#define Hn 8
#define DHn 64
#define Kn 7
#define Mn (Bn*Ln)
#define NEGV (-1e30f)
#define LDINV (1.0f/(float)(Ln*Dn))
#define TLC 8

// ---- big-GEMM tiling (BK=64, 1-term) ----
#define BK 64
#define PITCH 72
#define TB (128*PITCH*2)            // 18432 B
#define BUFB (2*TB)                 // 36864 B
#define SMEM_SZ (3*BUFB)            // 110592 B

// ---- fused attention smem (Q hi-only, KV chunk 64, 3-buffer ring) ----
#define AP 144
#define QT (128*AP)                 // 18432 B
#define KVT (64*AP)                 // 9216 B
#define KVB (2*KVT)                 // 18432 B
#define SMEM_ATT (QT + 3*KVB + 1024)    // 74752 B -> 2 CTAs/SM

// ======================= PTX helpers =======================
__device__ __forceinline__ uint32_t smem_u32(const void* p){
    uint32_t a;
    asm("{ .reg .u64 t; cvta.to.shared.u64 t, %1; cvt.u32.u64 %0, t; }" : "=r"(a) : "l"(p));
    return a;
}
__device__ __forceinline__ void cpasync16(uint32_t dst, const void* src){
    asm volatile("cp.async.cg.shared.global [%0], [%1], 16;" :: "r"(dst), "l"(src) : "memory");
}
#define CP_COMMIT() asm volatile("cp.async.commit_group;" ::: "memory")
#define CP_WAIT(N)  asm volatile("cp.async.wait_group %0;" :: "n"(N) : "memory")
__device__ __forceinline__ void ldsm4(uint32_t* r, uint32_t addr){
    asm volatile("ldmatrix.sync.aligned.m8n8.x4.shared.b16 {%0,%1,%2,%3}, [%4];"
        : "=r"(r[0]), "=r"(r[1]), "=r"(r[2]), "=r"(r[3]) : "r"(addr));
}
__device__ __forceinline__ void ldsm4t(uint32_t* r, uint32_t addr){
    asm volatile("ldmatrix.sync.aligned.m8n8.x4.trans.shared.b16 {%0,%1,%2,%3}, [%4];"
        : "=r"(r[0]), "=r"(r[1]), "=r"(r[2]), "=r"(r[3]) : "r"(addr));
}
__device__ __forceinline__ void mma16816(float* d, const uint32_t* a, const uint32_t* b){
    asm volatile("mma.sync.aligned.m16n8k16.row.col.f32.f16.f16.f32 "
        "{%0,%1,%2,%3}, {%4,%5,%6,%7}, {%8,%9}, {%0,%1,%2,%3};"
        : "+f"(d[0]), "+f"(d[1]), "+f"(d[2]), "+f"(d[3])
        : "r"(a[0]), "r"(a[1]), "r"(a[2]), "r"(a[3]), "r"(b[0]), "r"(b[1]));
}
__device__ __forceinline__ void packpair(float x, float y, uint32_t& hi, uint32_t& lo){
    __half hx = __float2half_rn(x), hy = __float2half_rn(y);
    __half2 h; h.x = hx; h.y = hy;
    __half2 l;
    l.x = __float2half_rn(x - __half2float(hx));
    l.y = __float2half_rn(y - __half2float(hy));
    hi = *(uint32_t*)&h; lo = *(uint32_t*)&l;
}
__device__ __forceinline__ uint32_t packhi(float x, float y){
    __half2 h; h.x = __float2half_rn(x); h.y = __float2half_rn(y);
    return *(uint32_t*)&h;
}
__device__ __forceinline__ float2 unpackpair(uint32_t hi, uint32_t lo){
    __half2 h = *(__half2*)&hi, l = *(__half2*)&lo;
    float2 r;
    r.x = __half2float(h.x) + __half2float(l.x);
    r.y = __half2float(h.y) + __half2float(l.y);
    return r;
}

// ======================= scratch =======================
__device__ float g_pS [4][Bn];
__device__ float g_pS2[4][Bn];
__device__ __half g_pA [Mn*Dn];
__device__ __half g_pX2[2][Mn*Dn];
__device__ __half g_pX1[2][Mn*Dn];
__device__ __half g_qkv[3][Mn*Dn];
__device__ __half g_w[8][Dn*Dn];

// ======================= weight prep + LN-partial zeroing =======================
__global__ void prep_weights(const float* __restrict__ pw_w,
                             const float* __restrict__ wq, const float* __restrict__ wk,
                             const float* __restrict__ wv,
                             const float* __restrict__ fc_w, const float* __restrict__ out_w)
{
    if (blockIdx.x == 0 && threadIdx.x < 4*Bn) {
        (&g_pS[0][0])[threadIdx.x]  = 0.f;
        (&g_pS2[0][0])[threadIdx.x] = 0.f;
    }
    int task = blockIdx.x >> 10;
    int idx  = (blockIdx.x & 1023) * 256 + threadIdx.x;
    if (task < 3) {
        g_w[task][idx] = __float2half_rn(pw_w[(size_t)task*Dn*Dn + idx]);
    } else if (task == 3) {
        int n = idx >> 9, d = idx & 511;
        int src = (n >> 6) * (Dn * DHn) + d * DHn + (n & 63);
        g_w[3][idx] = __float2half_rn(wq[src]);
        g_w[4][idx] = __float2half_rn(wk[src]);
        g_w[5][idx] = __float2half_rn(wv[src]);
    } else if (task == 4) {
        g_w[6][idx] = __float2half_rn(fc_w[idx]);
    } else {
        g_w[7][idx] = __float2half_rn(out_w[idx]);
    }
}

// ======================= sliding-window depthwise conv (4 ch/thread, TLC=8) =======================
__global__ void dwconv_pe(const float* __restrict__ x, const float* __restrict__ pe,
                          const float* __restrict__ w, const float* __restrict__ bias,
                          __half* __restrict__ hi)
{
    int idx = blockIdx.x * 256 + threadIdx.x;      // over Bn*(Ln/8)*(Dn/4) = 262144
    int d  = (idx & 127) << 2;
    int l0 = ((idx >> 7) & 63) << 3;
    int b  = idx >> 13;

    float wr[4][Kn];
#pragma unroll
    for (int c = 0; c < 4; c++)
#pragma unroll
        for (int kk = 0; kk < Kn; kk++) wr[c][kk] = w[(d + c)*Kn + kk];

    float4 bs = *(const float4*)(bias + d);
    float4 acc[TLC];
#pragma unroll
    for (int j = 0; j < TLC; j++) acc[j] = bs;

#pragma unroll
    for (int i = 0; i < TLC + 6; i++){
        int ll = l0 - 3 + i;
        if (ll >= 0 && ll < Ln){
            float4 xv = *(const float4*)(x + ((size_t)(b*Ln + ll))*Dn + d);
            float4 pv = *(const float4*)(pe + (size_t)ll*Dn + d);
            xv.x += pv.x; xv.y += pv.y; xv.z += pv.z; xv.w += pv.w;
#pragma unroll
            for (int kk = 0; kk < Kn; kk++){
                int j = i - kk;
                if (j >= 0 && j < TLC){
                    acc[j].x = fmaf(xv.x, wr[0][kk], acc[j].x);
                    acc[j].y = fmaf(xv.y, wr[1][kk], acc[j].y);
                    acc[j].z = fmaf(xv.z, wr[2][kk], acc[j].z);
                    acc[j].w = fmaf(xv.w, wr[3][kk], acc[j].w);
                }
            }
        }
    }
#pragma unroll
    for (int j = 0; j < TLC; j++){
        float vx = fmaxf(acc[j].x, 0.f), vy = fmaxf(acc[j].y, 0.f);
        float vz = fmaxf(acc[j].z, 0.f), vw = fmaxf(acc[j].w, 0.f);
        size_t o = ((size_t)(b*Ln + l0 + j))*Dn + d;
        uint2 hv; hv.x = packhi(vx, vy); hv.y = packhi(vz, vw);
        *(uint2*)(hi + o) = hv;
    }
}

__global__ void dwconv_pair(const __half* __restrict__ xh, const __half* __restrict__ xl,
                            const float* __restrict__ w, const float* __restrict__ bias,
                            __half* __restrict__ hi)
{
    int idx = blockIdx.x * 256 + threadIdx.x;
    int d  = (idx & 127) << 2;
    int l0 = ((idx >> 7) & 63) << 3;
    int b  = idx >> 13;

    float wr[4][Kn];
#pragma unroll
    for (int c = 0; c < 4; c++)
#pragma unroll
        for (int kk = 0; kk < Kn; kk++) wr[c][kk] = w[(d + c)*Kn + kk];

    float4 bs = *(const float4*)(bias + d);
    float4 acc[TLC];
#pragma unroll
    for (int j = 0; j < TLC; j++) acc[j] = bs;

#pragma unroll
    for (int i = 0; i < TLC + 6; i++){
        int ll = l0 - 3 + i;
        if (ll >= 0 && ll < Ln){
            size_t base = ((size_t)(b*Ln + ll))*Dn + d;
            uint2 hv = *(const uint2*)(xh + base);
            uint2 lv = *(const uint2*)(xl + base);
            float2 a0 = unpackpair(hv.x, lv.x);
            float2 a1 = unpackpair(hv.y, lv.y);
            float4 xv; xv.x = a0.x; xv.y = a0.y; xv.z = a1.x; xv.w = a1.y;
#pragma unroll
            for (int kk = 0; kk < Kn; kk++){
                int j = i - kk;
                if (j >= 0 && j < TLC){
                    acc[j].x = fmaf(xv.x, wr[0][kk], acc[j].x);
                    acc[j].y = fmaf(xv.y, wr[1][kk], acc[j].y);
                    acc[j].z = fmaf(xv.z, wr[2][kk], acc[j].z);
                    acc[j].w = fmaf(xv.w, wr[3][kk], acc[j].w);
                }
            }
        }
    }
#pragma unroll
    for (int j = 0; j < TLC; j++){
        float vx = fmaxf(acc[j].x, 0.f), vy = fmaxf(acc[j].y, 0.f);
        float vz = fmaxf(acc[j].z, 0.f), vw = fmaxf(acc[j].w, 0.f);
        size_t o = ((size_t)(b*Ln + l0 + j))*Dn + d;
        uint2 hv; hv.x = packhi(vx, vy); hv.y = packhi(vz, vw);
        *(uint2*)(hi + o) = hv;
    }
}

// ======================= mma.sync GEMM (1-term fp16, BK=64, 4x2 warps) =======================
template<bool RELU, int LNIN, int LNOUT, bool SPL, bool WRITEC>
__global__ __launch_bounds__(256, 2) void gemm_mma(
    const __half* __restrict__ Ahi, const __half* __restrict__ Whi,
    const float* __restrict__ bias, float* __restrict__ C,
    const __half* __restrict__ Rhi, const __half* __restrict__ Rlo,
    const float* __restrict__ lng, const float* __restrict__ lnb,
    __half* __restrict__ Chi, __half* __restrict__ Clo)
{
    extern __shared__ __align__(16) char dsm[];
    const uint32_t sb = smem_u32(dsm);
    const int tid = threadIdx.x;
    const int wid = tid >> 5, lane = tid & 31;
    const int warpRow = wid & 3, warpCol = wid >> 2;
    const int bx = blockIdx.x, by = blockIdx.y;

    const __half* srcs[2] = {Ahi, Whi};
    const int rowb[2] = { by*128, bx*128 };

    auto PREF = [&](int kt){
        uint32_t bufb = sb + (uint32_t)(kt % 3) * BUFB;
#pragma unroll
        for (int t = 0; t < 2; t++){
            const __half* src = srcs[t] + (size_t)rowb[t]*Dn + kt*BK;
            uint32_t tb = bufb + (uint32_t)t*TB;
#pragma unroll
            for (int i = 0; i < 4; i++){
                int id  = tid + i*256;
                int row = id >> 3, c = id & 7;
                cpasync16(tb + (uint32_t)(row*(PITCH*2) + c*16),
                          src + (size_t)row*Dn + c*8);
            }
        }
        CP_COMMIT();
    };

    float acc[2][8][4];
#pragma unroll
    for (int i = 0; i < 2; i++)
#pragma unroll
        for (int j = 0; j < 8; j++)
#pragma unroll
            for (int q = 0; q < 4; q++) acc[i][j][q] = 0.f;

    const uint32_t aRow = (uint32_t)(warpRow*32 + (lane & 15));
    const uint32_t aColB = (uint32_t)(((lane >> 4) << 4));
    const uint32_t bRow = (uint32_t)(warpCol*64 + (lane & 7) + ((lane >> 4) << 3));
    const uint32_t bColB = (uint32_t)((((lane >> 3) & 1) << 4));

    PREF(0);
    PREF(1);
#pragma unroll 1
    for (int kt = 0; kt < Dn/BK; kt++){
        if (kt + 1 < Dn/BK) { CP_WAIT(1); } else { CP_WAIT(0); }
        __syncthreads();
        if (kt + 2 < Dn/BK) PREF(kt + 2);

        uint32_t bufb = sb + (uint32_t)(kt % 3) * BUFB;
        uint32_t tAhi = bufb, tWhi = bufb + TB;
#pragma unroll
        for (int kk = 0; kk < 4; kk++){
            uint32_t ah[2][4], bh[4][4];
#pragma unroll
            for (int mi = 0; mi < 2; mi++)
                ldsm4(ah[mi], tAhi + (aRow + mi*16)*(PITCH*2) + aColB + kk*32);
#pragma unroll
            for (int nt = 0; nt < 4; nt++)
                ldsm4(bh[nt], tWhi + (bRow + nt*16)*(PITCH*2) + bColB + kk*32);
#pragma unroll
            for (int mi = 0; mi < 2; mi++)
#pragma unroll
                for (int nj = 0; nj < 8; nj++)
                    mma16816(acc[mi][nj], ah[mi], &bh[nj >> 1][(nj & 1) << 1]);
        }
    }

    float muv = 0.f, rsv = 0.f;
    if (LNIN >= 0) {
        int bb = (by*128) >> 9;
        float s = g_pS[LNIN][bb], s2 = g_pS2[LNIN][bb];
        muv = s * LDINV;
        rsv = rsqrtf(s2 * LDINV - muv*muv + 1e-5f);
    }
    const int r0base = by*128 + warpRow*32;
    const int c0base = bx*128 + warpCol*64;
    float ts = 0.f, ts2 = 0.f;
#pragma unroll
    for (int mi = 0; mi < 2; mi++){
#pragma unroll
        for (int rp = 0; rp < 2; rp++){
            int grow = r0base + mi*16 + (lane >> 2) + rp*8;
            int lrow = grow & (Ln - 1);
#pragma unroll
            for (int nj = 0; nj < 8; nj++){
                int col = c0base + nj*8 + (lane & 3)*2;
                float vx = acc[mi][nj][rp*2 + 0];
                float vy = acc[mi][nj][rp*2 + 1];
                float2 bs = *(const float2*)(bias + col);
                vx += bs.x; vy += bs.y;
                if (RELU) { vx = fmaxf(vx, 0.f); vy = fmaxf(vy, 0.f); }
                size_t off = (size_t)grow*Dn + col;
                if (LNIN >= 0) {
                    float2 rr = unpackpair(*(const uint32_t*)(Rhi + off),
                                           *(const uint32_t*)(Rlo + off));
                    float2 gg = *(const float2*)(lng + (size_t)lrow*Dn + col);
                    float2 bb = *(const float2*)(lnb + (size_t)lrow*Dn + col);
                    vx += (rr.x - muv)*rsv*gg.x + bb.x;
                    vy += (rr.y - muv)*rsv*gg.y + bb.y;
                }
                if (LNOUT >= 0) { ts += vx + vy; ts2 += vx*vx + vy*vy; }
                if (WRITEC) {
                    float2 o; o.x = vx; o.y = vy;
                    *(float2*)(C + off) = o;
                }
                if (SPL) {
                    uint32_t hi, lo;
                    packpair(vx, vy, hi, lo);
                    *(uint32_t*)(Chi + off) = hi;
                    *(uint32_t*)(Clo + off) = lo;
                }
            }
        }
    }
    if (LNOUT >= 0) {
#pragma unroll
        for (int o = 16; o > 0; o >>= 1){
            ts  += __shfl_xor_sync(0xffffffffu, ts,  o);
            ts2 += __shfl_xor_sync(0xffffffffu, ts2, o);
        }
        __shared__ float sred[2][8];
        if (lane == 0){ sred[0][wid] = ts; sred[1][wid] = ts2; }
        __syncthreads();
        if (tid == 0){
            float a = 0.f, b2 = 0.f;
#pragma unroll
            for (int i = 0; i < 8; i++){ a += sred[0][i]; b2 += sred[1][i]; }
            int batch = by >> 2;
            atomicAdd(&g_pS[LNOUT][batch],  a);
            atomicAdd(&g_pS2[LNOUT][batch], b2);
        }
    }
}

// ======================= merged qkv GEMM (1-term, BK=64) =======================
__global__ __launch_bounds__(256, 2) void gemm_qkv(
    const __half* __restrict__ Ahi,
    const float* __restrict__ bq, const float* __restrict__ bk, const float* __restrict__ bv)
{
    extern __shared__ __align__(16) char dsm[];
    const uint32_t sb = smem_u32(dsm);
    const int tid = threadIdx.x;
    const int wid = tid >> 5, lane = tid & 31;
    const int warpRow = wid & 3, warpCol = wid >> 2;
    const int bx = blockIdx.x, by = blockIdx.y;
    const int seg = bx >> 2, bxl = bx & 3;

    const __half* Whi = g_w[3 + seg];
    const float* bias = (seg == 0) ? bq : ((seg == 1) ? bk : bv);
    __half* Ch = g_qkv[seg];

    const __half* srcs[2] = {Ahi, Whi};
    const int rowb[2] = { by*128, bxl*128 };

    auto PREF = [&](int kt){
        uint32_t bufb = sb + (uint32_t)(kt % 3) * BUFB;
#pragma unroll
        for (int t = 0; t < 2; t++){
            const __half* src = srcs[t] + (size_t)rowb[t]*Dn + kt*BK;
            uint32_t tb = bufb + (uint32_t)t*TB;
#pragma unroll
            for (int i = 0; i < 4; i++){
                int id  = tid + i*256;
                int row = id >> 3, c = id & 7;
                cpasync16(tb + (uint32_t)(row*(PITCH*2) + c*16),
                          src + (size_t)row*Dn + c*8);
            }
        }
        CP_COMMIT();
    };

    float acc[2][8][4];
#pragma unroll
    for (int i = 0; i < 2; i++)
#pragma unroll
        for (int j = 0; j < 8; j++)
#pragma unroll
            for (int q = 0; q < 4; q++) acc[i][j][q] = 0.f;

    const uint32_t aRow = (uint32_t)(warpRow*32 + (lane & 15));
    const uint32_t aColB = (uint32_t)(((lane >> 4) << 4));
    const uint32_t bRow = (uint32_t)(warpCol*64 + (lane & 7) + ((lane >> 4) << 3));
    const uint32_t bColB = (uint32_t)((((lane >> 3) & 1) << 4));

    PREF(0);
    PREF(1);
#pragma unroll 1
    for (int kt = 0; kt < Dn/BK; kt++){
        if (kt + 1 < Dn/BK) { CP_WAIT(1); } else { CP_WAIT(0); }
        __syncthreads();
        if (kt + 2 < Dn/BK) PREF(kt + 2);

        uint32_t bufb = sb + (uint32_t)(kt % 3) * BUFB;
        uint32_t tAhi = bufb, tWhi = bufb + TB;
#pragma unroll
        for (int kk = 0; kk < 4; kk++){
            uint32_t ah[2][4], bh[4][4];
#pragma unroll
            for (int mi = 0; mi < 2; mi++)
                ldsm4(ah[mi], tAhi + (aRow + mi*16)*(PITCH*2) + aColB + kk*32);
#pragma unroll
            for (int nt = 0; nt < 4; nt++)
                ldsm4(bh[nt], tWhi + (bRow + nt*16)*(PITCH*2) + bColB + kk*32);
#pragma unroll
            for (int mi = 0; mi < 2; mi++)
#pragma unroll
                for (int nj = 0; nj < 8; nj++)
                    mma16816(acc[mi][nj], ah[mi], &bh[nj >> 1][(nj & 1) << 1]);
        }
    }

    const int r0base = by*128 + warpRow*32;
    const int c0base = bxl*128 + warpCol*64;
#pragma unroll
    for (int mi = 0; mi < 2; mi++){
#pragma unroll
        for (int rp = 0; rp < 2; rp++){
            int grow = r0base + mi*16 + (lane >> 2) + rp*8;
#pragma unroll
            for (int nj = 0; nj < 8; nj++){
                int col = c0base + nj*8 + (lane & 3)*2;
                float vx = acc[mi][nj][rp*2 + 0];
                float vy = acc[mi][nj][rp*2 + 1];
                float2 bs = *(const float2*)(bias + col);
                vx += bs.x; vy += bs.y;
                *(uint32_t*)(Ch + (size_t)grow*Dn + col) = packhi(vx, vy);
            }
        }
    }
}

// ======================= fused flash attention (fp16, 3-buffer KV ring) =======================
__global__ __launch_bounds__(256, 2) void attn_fused(
    const __half* __restrict__ qh,
    const __half* __restrict__ kh, const __half* __restrict__ vh,
    const float* __restrict__ mask,
    __half* __restrict__ Ohi)
{
    extern __shared__ __align__(16) char dsm[];
    const uint32_t sb = smem_u32(dsm);
    const int tid = threadIdx.x, wid = tid >> 5, lane = tid & 31;
    const int bh = blockIdx.y, b = bh >> 3, h = bh & 7;
    const int i0 = blockIdx.x * 128;
    const size_t qoff = ((size_t)(b*Ln + i0))*Dn + h*DHn;
    const size_t koff = ((size_t)(b*Ln))*Dn + h*DHn;

    const uint32_t smQh = sb;
    const uint32_t smKV0 = sb + QT;
    const uint32_t smMaskOff = QT + 3*KVB;

    auto LOADC = [&](int c){
        int slot = c % 3;
        uint32_t base = smKV0 + (uint32_t)slot*KVB;
        size_t g0 = koff + (size_t)(c*64)*Dn;
#pragma unroll
        for (int i = 0; i < 2; i++){
            int id = tid + i*256; int row = id >> 3, seg = id & 7;
            size_t go = g0 + (size_t)row*Dn + seg*8;
            uint32_t so = (uint32_t)(row*AP + seg*16);
            cpasync16(base + so,       kh + go);
            cpasync16(base + KVT + so, vh + go);
        }
        if (tid < 16)
            cpasync16(sb + smMaskOff + (uint32_t)slot*256 + tid*16,
                      mask + b*Ln + c*64 + tid*4);
        CP_COMMIT();
    };

#pragma unroll
    for (int i = 0; i < 4; i++){
        int id = tid + i*256; int row = id >> 3, seg = id & 7;
        cpasync16(smQh + (uint32_t)(row*AP + seg*16),
                  qh + qoff + (size_t)row*Dn + seg*8);
    }
    LOADC(0);
    LOADC(1);

    const int g = lane >> 2, t4 = lane & 3;
    float mi0 = mask[b*Ln + i0 + wid*16 + g];
    float mi1 = mask[b*Ln + i0 + wid*16 + g + 8];

    float m0 = -3.0e38f, m1 = -3.0e38f, l0 = 0.f, l1 = 0.f;
    float o[8][4];
#pragma unroll
    for (int i = 0; i < 8; i++)
#pragma unroll
        for (int j = 0; j < 4; j++) o[i][j] = 0.f;

    const uint32_t aQoff = (uint32_t)((wid*16 + (lane & 15))*AP + ((lane >> 4) << 4));
    const uint32_t bKoff = (uint32_t)(((lane & 7) + ((lane >> 4) << 3))*AP + (((lane >> 3) & 1) << 4));
    const uint32_t vOff  = (uint32_t)((lane & 15)*AP + ((lane >> 4) << 4));

#pragma unroll 1
    for (int c = 0; c < 8; c++){
        if (c < 7) { CP_WAIT(1); } else { CP_WAIT(0); }
        __syncthreads();                     // data ready + buf (c+2)%3 free (read at c-1)
        if (c < 6) LOADC(c + 2);
        int slot = c % 3;
        const uint32_t kb = smKV0 + (uint32_t)slot*KVB;
        const float* mjp = (const float*)(dsm + smMaskOff + slot*256);

        float s[8][4];
#pragma unroll
        for (int nj = 0; nj < 8; nj++)
#pragma unroll
            for (int q = 0; q < 4; q++) s[nj][q] = 0.f;
#pragma unroll
        for (int ss = 0; ss < 4; ss++){
            uint32_t ah[4];
            ldsm4(ah, smQh + aQoff + ss*32);
#pragma unroll
            for (int njp = 0; njp < 4; njp++){
                uint32_t bhh[4];
                ldsm4(bhh, kb + (uint32_t)(njp*16)*AP + bKoff + ss*32);
                mma16816(s[2*njp],   ah, &bhh[0]);
                mma16816(s[2*njp+1], ah, &bhh[2]);
            }
        }

        float rm0 = -3.0e38f, rm1 = -3.0e38f;
#pragma unroll
        for (int nj = 0; nj < 8; nj++){
            int colb = nj*8 + t4*2;
            float mj0 = mjp[colb], mj1 = mjp[colb+1];
            float mm;
            mm = mi0*mj0; s[nj][0] = s[nj][0]*0.125f*mm + NEGV*(1.f - mm);
            mm = mi0*mj1; s[nj][1] = s[nj][1]*0.125f*mm + NEGV*(1.f - mm);
            mm = mi1*mj0; s[nj][2] = s[nj][2]*0.125f*mm + NEGV*(1.f - mm);
            mm = mi1*mj1; s[nj][3] = s[nj][3]*0.125f*mm + NEGV*(1.f - mm);
            rm0 = fmaxf(rm0, fmaxf(s[nj][0], s[nj][1]));
            rm1 = fmaxf(rm1, fmaxf(s[nj][2], s[nj][3]));
        }
        rm0 = fmaxf(rm0, __shfl_xor_sync(0xffffffffu, rm0, 1));
        rm0 = fmaxf(rm0, __shfl_xor_sync(0xffffffffu, rm0, 2));
        rm1 = fmaxf(rm1, __shfl_xor_sync(0xffffffffu, rm1, 1));
        rm1 = fmaxf(rm1, __shfl_xor_sync(0xffffffffu, rm1, 2));
        float nm0 = fmaxf(m0, rm0), nm1 = fmaxf(m1, rm1);
        float al0 = __expf(m0 - nm0), al1 = __expf(m1 - nm1);
        m0 = nm0; m1 = nm1;
#pragma unroll
        for (int nd = 0; nd < 8; nd++){
            o[nd][0] *= al0; o[nd][1] *= al0;
            o[nd][2] *= al1; o[nd][3] *= al1;
        }

        float sum0 = 0.f, sum1 = 0.f;
#pragma unroll
        for (int ss = 0; ss < 4; ss++){
            float p00 = __expf(s[2*ss][0]   - nm0), p01 = __expf(s[2*ss][1]   - nm0);
            float p02 = __expf(s[2*ss][2]   - nm1), p03 = __expf(s[2*ss][3]   - nm1);
            float p10 = __expf(s[2*ss+1][0] - nm0), p11 = __expf(s[2*ss+1][1] - nm0);
            float p12 = __expf(s[2*ss+1][2] - nm1), p13 = __expf(s[2*ss+1][3] - nm1);
            sum0 += p00 + p01 + p10 + p11;
            sum1 += p02 + p03 + p12 + p13;
            uint32_t pah[4];
            pah[0] = packhi(p00, p01);
            pah[1] = packhi(p02, p03);
            pah[2] = packhi(p10, p11);
            pah[3] = packhi(p12, p13);
#pragma unroll
            for (int ndp = 0; ndp < 4; ndp++){
                uint32_t vhh[4];
                ldsm4t(vhh, kb + KVT + (uint32_t)(ss*16)*AP + vOff + ndp*32);
                mma16816(o[2*ndp],   pah, &vhh[0]);
                mma16816(o[2*ndp+1], pah, &vhh[2]);
            }
        }
        sum0 += __shfl_xor_sync(0xffffffffu, sum0, 1);
        sum0 += __shfl_xor_sync(0xffffffffu, sum0, 2);
        sum1 += __shfl_xor_sync(0xffffffffu, sum1, 1);
        sum1 += __shfl_xor_sync(0xffffffffu, sum1, 2);
        l0 = l0*al0 + sum0;
        l1 = l1*al1 + sum1;
    }

    float inv0 = 1.f / l0, inv1 = 1.f / l1;
    int r0 = i0 + wid*16 + g, r1 = r0 + 8;
    size_t ob = ((size_t)(b*Ln))*Dn + h*DHn;
#pragma unroll
    for (int nd = 0; nd < 8; nd++){
        int col = nd*8 + t4*2;
        *(uint32_t*)(Ohi + ob + (size_t)r0*Dn + col) = packhi(o[nd][0]*inv0, o[nd][1]*inv0);
        *(uint32_t*)(Ohi + ob + (size_t)r1*Dn + col) = packhi(o[nd][2]*inv1, o[nd][3]*inv1);
    }
}

// ======================= host orchestration =======================
extern "C" void kernel_launch(void* const* d_in, const int* in_sizes, int n_in,
                              void* d_out, int out_size)
{
    (void)in_sizes; (void)n_in; (void)out_size;
    const float* x     = (const float*)d_in[0];
    const float* mask  = (const float*)d_in[1];
    const float* pe    = (const float*)d_in[2];
    const float* dw_w  = (const float*)d_in[3];
    const float* dw_b  = (const float*)d_in[4];
    const float* pw_w  = (const float*)d_in[5];
    const float* pw_b  = (const float*)d_in[6];
    const float* wq    = (const float*)d_in[7];
    const float* bq    = (const float*)d_in[8];
    const float* wk    = (const float*)d_in[9];
    const float* bk    = (const float*)d_in[10];
    const float* wv    = (const float*)d_in[11];
    const float* bv    = (const float*)d_in[12];
    const float* fc_w  = (const float*)d_in[13];
    const float* fc_b  = (const float*)d_in[14];
    const float* out_w = (const float*)d_in[15];
    const float* out_b = (const float*)d_in[16];
    const float* lnc_g = (const float*)d_in[17];
    const float* lnc_b = (const float*)d_in[18];
    const float* lna_g = (const float*)d_in[19];
    const float* lna_b = (const float*)d_in[20];
    const float* lno_g = (const float*)d_in[21];
    const float* lno_b = (const float*)d_in[22];
    float* out = (float*)d_out;

    __half *pA, *pX2, *pX1, *qkv;
    cudaGetSymbolAddress((void**)&pA,  g_pA);
    cudaGetSymbolAddress((void**)&pX2, g_pX2);
    cudaGetSymbolAddress((void**)&pX1, g_pX1);
    cudaGetSymbolAddress((void**)&qkv, g_qkv);
    __half* wsym;
    cudaGetSymbolAddress((void**)&wsym, g_w);

    const size_t NN = (size_t)Mn*Dn;
    __half *x2_h = pX2, *x2_l = pX2 + NN;
    __half *x1_h = pX1, *x1_l = pX1 + NN;
    __half *q_h = qkv, *k_h = qkv + NN, *v_h = qkv + 2*NN;
    auto W = [&](int i){ return wsym + (size_t)i * Dn * Dn; };

    cudaFuncSetAttribute(gemm_mma<true,-1,0,true,false>,  cudaFuncAttributeMaxDynamicSharedMemorySize, SMEM_SZ);
    cudaFuncSetAttribute(gemm_mma<true,0,1,true,false>,   cudaFuncAttributeMaxDynamicSharedMemorySize, SMEM_SZ);
    cudaFuncSetAttribute(gemm_mma<true,1,2,true,false>,   cudaFuncAttributeMaxDynamicSharedMemorySize, SMEM_SZ);
    cudaFuncSetAttribute(gemm_mma<false,2,3,true,false>,  cudaFuncAttributeMaxDynamicSharedMemorySize, SMEM_SZ);
    cudaFuncSetAttribute(gemm_mma<false,3,-1,false,true>, cudaFuncAttributeMaxDynamicSharedMemorySize, SMEM_SZ);
    cudaFuncSetAttribute(gemm_qkv, cudaFuncAttributeMaxDynamicSharedMemorySize, SMEM_SZ);
    cudaFuncSetAttribute(attn_fused, cudaFuncAttributeMaxDynamicSharedMemorySize, SMEM_ATT);

    const int DWB = (Bn * (Ln/TLC) * (Dn/4)) / 256;   // 1024 blocks
    dim3 gemmGrid(Dn/128, Mn/128);      // (4, 128)
    dim3 qkvGrid(12, Mn/128);           // N = 1536

    // 1. weight prep + LN-partial zeroing
    prep_weights<<<6*1024, 256>>>(pw_w, wq, wk, wv, fc_w, out_w);

    // 2-3. conv layer 0 (PE fused); stats -> slot 0 (lnc0)
    dwconv_pe<<<DWB, 256>>>(x, pe, dw_w + 0*Dn*Kn, dw_b + 0*Dn, pA);
    gemm_mma<true,-1,0,true,false><<<gemmGrid, 256, SMEM_SZ>>>(
        pA, W(0), pw_b + 0*Dn, nullptr,
        nullptr, nullptr, nullptr, nullptr, x2_h, x2_l);
    // 4-5. conv layer 1: + LN(x2; lnc0, slot 0); stats -> slot 1 (lnc1)
    dwconv_pair<<<DWB, 256>>>(x2_h, x2_l, dw_w + 1*Dn*Kn, dw_b + 1*Dn, pA);
    gemm_mma<true,0,1,true,false><<<gemmGrid, 256, SMEM_SZ>>>(
        pA, W(1), pw_b + 1*Dn, nullptr,
        x2_h, x2_l, lnc_g + 0, lnc_b + 0, x1_h, x1_l);
    // 6-7. conv layer 2: + LN(x1; lnc1, slot 1); stats -> slot 2 (lna)
    dwconv_pair<<<DWB, 256>>>(x1_h, x1_l, dw_w + 2*Dn*Kn, dw_b + 2*Dn, pA);
    gemm_mma<true,1,2,true,false><<<gemmGrid, 256, SMEM_SZ>>>(
        pA, W(2), pw_b + 2*Dn, nullptr,
        x1_h, x1_l, lnc_g + Ln*Dn, lnc_b + Ln*Dn, x2_h, x2_l);

    // 8. merged qkv projection
    gemm_qkv<<<qkvGrid, 256, SMEM_SZ>>>(x2_h, bq, bk, bv);

    // 9. fused flash attention -> pA (hi only)
    attn_fused<<<dim3(Ln/128, Bn*Hn), 256, SMEM_ATT>>>(
        q_h, k_h, v_h, mask, pA);

    // 10. fc + LN(x2; lna, slot 2) -> x1 pair; stats -> slot 3 (lno)
    gemm_mma<false,2,3,true,false><<<gemmGrid, 256, SMEM_SZ>>>(
        pA, W(6), fc_b, nullptr,
        x2_h, x2_l, lna_g, lna_b, x1_h, x1_l);

    // 11. out + LN(x1; lno, slot 3) -> d_out (fp32)
    gemm_mma<false,3,-1,false,true><<<gemmGrid, 256, SMEM_SZ>>>(
        x1_h, W(7), out_b, out,
        x1_h, x1_l, lno_g, lno_b, nullptr, nullptr);
}